// round 11
// baseline (speedup 1.0000x reference)
#include <cuda_runtime.h>

// ============================================================================
// Cross attention (b=2, n=8192, m=32, DIM=256, 8 heads x 32), reassociated:
//   K1: Q   = X @ Wq                         [T,256]
//   K2: QK_h = Q_h @ Wk_h^T * SCALE          [8][T,256]   (K=32 batched GEMM)
//   K3: dots[h,m]=qk_h.y_m ; softmax ; z_h = attn_h @ y   [8][T,256]  (fused)
//   K4: O_h = Z_h @ Wv_h                     [T,256] interleaved by head
//   K5: OUT = O @ Wout + bout                [T,256]
// All fp32. ~12.9 GFLOP total vs ~137 GFLOP naive; y read from DRAM once.
// ============================================================================

#define T_MAX 16384
#define SCALE 0.17677669529663689f   // 32^-0.5

__device__ __align__(128) float g_Q [T_MAX * 256];        //  16 MB
__device__ __align__(128) float g_QK[8 * T_MAX * 256];    // 128 MB  [h][t][i]
__device__ __align__(128) float g_Z [8 * T_MAX * 256];    // 128 MB  [h][t][i]
__device__ __align__(128) float g_O1[T_MAX * 256];        //  16 MB

// ----------------------------------------------------------------------------
// Tiled SGEMM: C = alpha * A @ op(B) (+bias), batched over blockIdx.z.
//   A: [M,K] row-major (lda). B: !TRANSB -> [K,N] (ldb); TRANSB -> [N,K] (ldb).
//   256 threads, BK=16, 8x4 register microtile. BM = 8 * (256 / (BN/4)).
// ----------------------------------------------------------------------------
template<int BM, int BN, bool TRANSB>
__global__ __launch_bounds__(256)
void gemm_kernel(const float* __restrict__ A, int lda, long sAz,
                 const float* __restrict__ B, int ldb, long sBz,
                 float* __restrict__ C, int ldc, long sCz,
                 int M, int N, int K,
                 const float* __restrict__ bias, float alpha)
{
    constexpr int BK = 16;
    constexpr int TX = BN / 4;
    constexpr int TY = 256 / TX;
    static_assert(BM == TY * 8, "tile mismatch");

    __shared__ __align__(16) float As[BK][BM];
    __shared__ __align__(16) float Bs[BK][BN];

    A += (size_t)blockIdx.z * sAz;
    B += (size_t)blockIdx.z * sBz;
    C += (size_t)blockIdx.z * sCz;

    const int tid = threadIdx.x;
    const int tx = tid % TX;
    const int ty = tid / TX;
    const int row0 = blockIdx.y * BM;
    const int col0 = blockIdx.x * BN;

    float acc[8][4];
#pragma unroll
    for (int i = 0; i < 8; i++)
#pragma unroll
        for (int j = 0; j < 4; j++) acc[i][j] = 0.f;

    for (int kb = 0; kb < K; kb += BK) {
        // stage A (transposed into As[k][m])
        for (int f = tid; f < BM * (BK / 4); f += 256) {
            int m  = f / (BK / 4);
            int k4 = (f % (BK / 4)) * 4;
            float4 v = make_float4(0.f, 0.f, 0.f, 0.f);
            int gr = row0 + m;
            if (gr < M)
                v = *reinterpret_cast<const float4*>(A + (size_t)gr * lda + kb + k4);
            As[k4 + 0][m] = v.x; As[k4 + 1][m] = v.y;
            As[k4 + 2][m] = v.z; As[k4 + 3][m] = v.w;
        }
        // stage B (Bs[k][n])
        if (!TRANSB) {
            for (int f = tid; f < BK * (BN / 4); f += 256) {
                int k  = f / (BN / 4);
                int n4 = (f % (BN / 4)) * 4;
                float4 v = *reinterpret_cast<const float4*>(
                    B + (size_t)(kb + k) * ldb + col0 + n4);
                *reinterpret_cast<float4*>(&Bs[k][n4]) = v;
            }
        } else {
            for (int f = tid; f < BN * (BK / 4); f += 256) {
                int n  = f / (BK / 4);
                int k4 = (f % (BK / 4)) * 4;
                float4 v = *reinterpret_cast<const float4*>(
                    B + (size_t)(col0 + n) * ldb + kb + k4);
                Bs[k4 + 0][n] = v.x; Bs[k4 + 1][n] = v.y;
                Bs[k4 + 2][n] = v.z; Bs[k4 + 3][n] = v.w;
            }
        }
        __syncthreads();

#pragma unroll
        for (int kk = 0; kk < BK; kk++) {
            float a[8], b[4];
            *reinterpret_cast<float4*>(&a[0]) =
                *reinterpret_cast<const float4*>(&As[kk][ty * 8]);
            *reinterpret_cast<float4*>(&a[4]) =
                *reinterpret_cast<const float4*>(&As[kk][ty * 8 + 4]);
            *reinterpret_cast<float4*>(&b[0]) =
                *reinterpret_cast<const float4*>(&Bs[kk][tx * 4]);
#pragma unroll
            for (int i = 0; i < 8; i++)
#pragma unroll
                for (int j = 0; j < 4; j++)
                    acc[i][j] = fmaf(a[i], b[j], acc[i][j]);
        }
        __syncthreads();
    }

#pragma unroll
    for (int i = 0; i < 8; i++) {
        int gr = row0 + ty * 8 + i;
        int gc = col0 + tx * 4;
        if (gr < M && gc < N) {
            float4 v;
            v.x = acc[i][0] * alpha; v.y = acc[i][1] * alpha;
            v.z = acc[i][2] * alpha; v.w = acc[i][3] * alpha;
            if (bias) {
                v.x += bias[gc + 0]; v.y += bias[gc + 1];
                v.z += bias[gc + 2]; v.w += bias[gc + 3];
            }
            *reinterpret_cast<float4*>(C + (size_t)gr * ldc + gc) = v;
        }
    }
}

// ----------------------------------------------------------------------------
// K3: fused attention core. One block per token, 256 threads (8 warps).
//   Y  [T][32][256]   QK [8][T][256] (pre-scaled)   Z [8][T][256]
// y staged once into XOR-swizzled smem (conflict-free in all phases).
// dots: warp c owns i4-chunk [8c,8c+8), lanes = m; y register-cached across
//       all 8 heads; cross-warp partial reduce through smem.
// softmax: warp-shuffle (warp h holds all 32 m in its lanes).
// z: 4 m-groups x 64 i4 columns, y register-reused across 8 heads, 4-way
//    partial reduce through smem, float4 coalesced store.
// Dynamic smem: 82944 B.
// ----------------------------------------------------------------------------
__global__ __launch_bounds__(256)
void attn_kernel(const float* __restrict__ Y,
                 const float* __restrict__ QK,
                 float* __restrict__ Z,
                 int T)
{
    extern __shared__ __align__(16) char smem_raw[];
    float4* ys4  = reinterpret_cast<float4*>(smem_raw);   // [32][64] swizzled
    float4* qks4 = ys4 + 2048;                            // [8][64]
    float*  pd   = reinterpret_cast<float*>(qks4 + 512);  // [8c][8h][32m]
    float*  attn = pd + 2048;                             // [8h][32m]
    float4* zp   = reinterpret_cast<float4*>(attn + 256); // [4g][8h][64i4]

    const int tid = threadIdx.x;
    const int t   = blockIdx.x;

    // ---- stage y (swizzled) and qk ----
    const float4* Y4 = reinterpret_cast<const float4*>(Y + (size_t)t * 32 * 256);
#pragma unroll 4
    for (int f = tid; f < 2048; f += 256) {
        int m = f >> 6, i4 = f & 63;
        ys4[m * 64 + ((i4 + m) & 63)] = Y4[f];
    }
    const float4* QK4 = reinterpret_cast<const float4*>(QK);
#pragma unroll
    for (int f = tid; f < 512; f += 256) {
        int h = f >> 6, i4 = f & 63;
        qks4[f] = QK4[((size_t)h * T + t) * 64 + i4];
    }
    __syncthreads();

    // ---- dots: warp c = i4-chunk, lane = m ----
    {
        const int c = tid >> 5, m = tid & 31;
        float4 yreg[8];
#pragma unroll
        for (int j = 0; j < 8; j++)
            yreg[j] = ys4[m * 64 + (((c << 3) + j + m) & 63)];
#pragma unroll
        for (int h = 0; h < 8; h++) {
            float s = 0.f;
#pragma unroll
            for (int j = 0; j < 8; j++) {
                float4 q4 = qks4[h * 64 + (c << 3) + j];
                s = fmaf(yreg[j].x, q4.x, s);
                s = fmaf(yreg[j].y, q4.y, s);
                s = fmaf(yreg[j].z, q4.z, s);
                s = fmaf(yreg[j].w, q4.w, s);
            }
            pd[(c * 8 + h) * 32 + m] = s;
        }
    }
    __syncthreads();

    // ---- reduce partials + softmax (warp = head) ----
    {
        const int h = tid >> 5, m = tid & 31;
        float d = 0.f;
#pragma unroll
        for (int cc = 0; cc < 8; cc++) d += pd[(cc * 8 + h) * 32 + m];
        float mx = d;
#pragma unroll
        for (int o = 16; o > 0; o >>= 1)
            mx = fmaxf(mx, __shfl_xor_sync(0xffffffffu, mx, o));
        float e = __expf(d - mx);
        float sm = e;
#pragma unroll
        for (int o = 16; o > 0; o >>= 1)
            sm += __shfl_xor_sync(0xffffffffu, sm, o);
        attn[h * 32 + m] = e / sm;
    }
    __syncthreads();

    // ---- z: group g = 8 m's, column i4; y register-reused across 8 heads ----
    {
        const int g = tid >> 6, i4 = tid & 63;
        float4 acc[8];
#pragma unroll
        for (int h = 0; h < 8; h++) acc[h] = make_float4(0.f, 0.f, 0.f, 0.f);
#pragma unroll
        for (int mm = 0; mm < 8; mm++) {
            int m = g * 8 + mm;
            float4 y4 = ys4[m * 64 + ((i4 + m) & 63)];
#pragma unroll
            for (int h = 0; h < 8; h++) {
                float a = attn[h * 32 + m];
                acc[h].x = fmaf(a, y4.x, acc[h].x);
                acc[h].y = fmaf(a, y4.y, acc[h].y);
                acc[h].z = fmaf(a, y4.z, acc[h].z);
                acc[h].w = fmaf(a, y4.w, acc[h].w);
            }
        }
#pragma unroll
        for (int h = 0; h < 8; h++)
            zp[(g * 8 + h) * 64 + i4] = acc[h];
    }
    __syncthreads();

    // ---- reduce 4 groups, store Z ----
    float4* Z4 = reinterpret_cast<float4*>(Z);
#pragma unroll
    for (int r = 0; r < 2; r++) {
        int idx = tid + (r << 8);
        int h = idx >> 6, i4 = idx & 63;
        float4 s0 = zp[(0  + h) * 64 + i4];
        float4 s1 = zp[(8  + h) * 64 + i4];
        float4 s2 = zp[(16 + h) * 64 + i4];
        float4 s3 = zp[(24 + h) * 64 + i4];
        float4 s;
        s.x = (s0.x + s1.x) + (s2.x + s3.x);
        s.y = (s0.y + s1.y) + (s2.y + s3.y);
        s.z = (s0.z + s1.z) + (s2.z + s3.z);
        s.w = (s0.w + s1.w) + (s2.w + s3.w);
        Z4[((size_t)h * T + t) * 64 + i4] = s;
    }
}

// ----------------------------------------------------------------------------
extern "C" void kernel_launch(void* const* d_in, const int* in_sizes, int n_in,
                              void* d_out, int out_size)
{
    const float* x    = (const float*)d_in[0];
    const float* y    = (const float*)d_in[1];
    const float* Wq   = (const float*)d_in[2];
    const float* Wkv  = (const float*)d_in[3];
    const float* Wout = (const float*)d_in[4];
    const float* bout = (const float*)d_in[5];
    float* out = (float*)d_out;

    const int T = in_sizes[0] / 256;   // b*n = 16384

    float *Q, *QK, *Z, *O1;
    cudaGetSymbolAddress((void**)&Q,  g_Q);
    cudaGetSymbolAddress((void**)&QK, g_QK);
    cudaGetSymbolAddress((void**)&Z,  g_Z);
    cudaGetSymbolAddress((void**)&O1, g_O1);

    const int ATTN_SMEM = 82944;
    cudaFuncSetAttribute(attn_kernel,
                         cudaFuncAttributeMaxDynamicSharedMemorySize, ATTN_SMEM);

    // K1: Q = X @ Wq   [T,256] = [T,256]@[256,256]
    gemm_kernel<128, 64, false><<<dim3(4, T / 128, 1), 256>>>(
        x, 256, 0,  Wq, 256, 0,  Q, 256, 0,  T, 256, 256, nullptr, 1.f);

    // K2: QK_h = Q_h @ Wk_h^T * SCALE   batched over h (z-dim)
    //     A = Q cols [h*32, h*32+32), B = Wkv rows as [N=256(i), K=32(d)]
    gemm_kernel<128, 64, true><<<dim3(4, T / 128, 8), 256>>>(
        Q, 256, 32,  Wkv, 512, 32,  QK, 256, (long)T * 256,
        T, 256, 32, nullptr, SCALE);

    // K3: fused dots/softmax/z
    attn_kernel<<<T, 256, ATTN_SMEM>>>(y, QK, Z, T);

    // K4: O_h = Z_h @ Wv_h   [T,32] per head, interleaved into O1[t][h*32+d]
    gemm_kernel<256, 32, false><<<dim3(1, T / 256, 8), 256>>>(
        Z, 256, (long)T * 256,  Wkv + 256, 512, 32,  O1, 256, 32,
        T, 32, 256, nullptr, 1.f);

    // K5: OUT = O1 @ Wout + bout
    gemm_kernel<128, 64, false><<<dim3(4, T / 128, 1), 256>>>(
        O1, 256, 0,  Wout, 256, 0,  out, 256, 0,
        T, 256, 256, bout, 1.f);
}

// round 12
// speedup vs baseline: 1.0002x; 1.0002x over previous
#include <cuda_runtime.h>

// ============================================================================
// Cross attention (b=2, n=8192, m=32, DIM=256, 8 heads x 32), reassociated:
//   K1: Q   = X @ Wq                         [T,256]
//   K2: QK_h = Q_h @ Wk_h^T * SCALE          [8][T,256]   (K=32 batched GEMM)
//   K3: dots[h,m]=qk_h.y_m ; softmax ; z_h = attn_h @ y   [8][T,256]  (fused)
//   K4: O_h = Z_h @ Wv_h                     [T,256] interleaved by head
//   K5: OUT = O @ Wout + bout                [T,256]
// All fp32. ~12.9 GFLOP total vs ~137 GFLOP naive; y read from DRAM once.
// ============================================================================

#define T_MAX 16384
#define SCALE 0.17677669529663689f   // 32^-0.5

__device__ __align__(128) float g_Q [T_MAX * 256];        //  16 MB
__device__ __align__(128) float g_QK[8 * T_MAX * 256];    // 128 MB  [h][t][i]
__device__ __align__(128) float g_Z [8 * T_MAX * 256];    // 128 MB  [h][t][i]
__device__ __align__(128) float g_O1[T_MAX * 256];        //  16 MB

// ----------------------------------------------------------------------------
// Tiled SGEMM: C = alpha * A @ op(B) (+bias), batched over blockIdx.z.
//   A: [M,K] row-major (lda). B: !TRANSB -> [K,N] (ldb); TRANSB -> [N,K] (ldb).
//   256 threads, BK=16, 8x4 register microtile. BM = 8 * (256 / (BN/4)).
// ----------------------------------------------------------------------------
template<int BM, int BN, bool TRANSB>
__global__ __launch_bounds__(256)
void gemm_kernel(const float* __restrict__ A, int lda, long sAz,
                 const float* __restrict__ B, int ldb, long sBz,
                 float* __restrict__ C, int ldc, long sCz,
                 int M, int N, int K,
                 const float* __restrict__ bias, float alpha)
{
    constexpr int BK = 16;
    constexpr int TX = BN / 4;
    constexpr int TY = 256 / TX;
    static_assert(BM == TY * 8, "tile mismatch");

    __shared__ __align__(16) float As[BK][BM];
    __shared__ __align__(16) float Bs[BK][BN];

    A += (size_t)blockIdx.z * sAz;
    B += (size_t)blockIdx.z * sBz;
    C += (size_t)blockIdx.z * sCz;

    const int tid = threadIdx.x;
    const int tx = tid % TX;
    const int ty = tid / TX;
    const int row0 = blockIdx.y * BM;
    const int col0 = blockIdx.x * BN;

    float acc[8][4];
#pragma unroll
    for (int i = 0; i < 8; i++)
#pragma unroll
        for (int j = 0; j < 4; j++) acc[i][j] = 0.f;

    for (int kb = 0; kb < K; kb += BK) {
        // stage A (transposed into As[k][m])
        for (int f = tid; f < BM * (BK / 4); f += 256) {
            int m  = f / (BK / 4);
            int k4 = (f % (BK / 4)) * 4;
            float4 v = make_float4(0.f, 0.f, 0.f, 0.f);
            int gr = row0 + m;
            if (gr < M)
                v = *reinterpret_cast<const float4*>(A + (size_t)gr * lda + kb + k4);
            As[k4 + 0][m] = v.x; As[k4 + 1][m] = v.y;
            As[k4 + 2][m] = v.z; As[k4 + 3][m] = v.w;
        }
        // stage B (Bs[k][n])
        if (!TRANSB) {
            for (int f = tid; f < BK * (BN / 4); f += 256) {
                int k  = f / (BN / 4);
                int n4 = (f % (BN / 4)) * 4;
                float4 v = *reinterpret_cast<const float4*>(
                    B + (size_t)(kb + k) * ldb + col0 + n4);
                *reinterpret_cast<float4*>(&Bs[k][n4]) = v;
            }
        } else {
            for (int f = tid; f < BN * (BK / 4); f += 256) {
                int n  = f / (BK / 4);
                int k4 = (f % (BK / 4)) * 4;
                float4 v = *reinterpret_cast<const float4*>(
                    B + (size_t)(col0 + n) * ldb + kb + k4);
                Bs[k4 + 0][n] = v.x; Bs[k4 + 1][n] = v.y;
                Bs[k4 + 2][n] = v.z; Bs[k4 + 3][n] = v.w;
            }
        }
        __syncthreads();

#pragma unroll
        for (int kk = 0; kk < BK; kk++) {
            float a[8], b[4];
            *reinterpret_cast<float4*>(&a[0]) =
                *reinterpret_cast<const float4*>(&As[kk][ty * 8]);
            *reinterpret_cast<float4*>(&a[4]) =
                *reinterpret_cast<const float4*>(&As[kk][ty * 8 + 4]);
            *reinterpret_cast<float4*>(&b[0]) =
                *reinterpret_cast<const float4*>(&Bs[kk][tx * 4]);
#pragma unroll
            for (int i = 0; i < 8; i++)
#pragma unroll
                for (int j = 0; j < 4; j++)
                    acc[i][j] = fmaf(a[i], b[j], acc[i][j]);
        }
        __syncthreads();
    }

#pragma unroll
    for (int i = 0; i < 8; i++) {
        int gr = row0 + ty * 8 + i;
        int gc = col0 + tx * 4;
        if (gr < M && gc < N) {
            float4 v;
            v.x = acc[i][0] * alpha; v.y = acc[i][1] * alpha;
            v.z = acc[i][2] * alpha; v.w = acc[i][3] * alpha;
            if (bias) {
                v.x += bias[gc + 0]; v.y += bias[gc + 1];
                v.z += bias[gc + 2]; v.w += bias[gc + 3];
            }
            *reinterpret_cast<float4*>(C + (size_t)gr * ldc + gc) = v;
        }
    }
}

// ----------------------------------------------------------------------------
// K3: fused attention core. One block per token, 256 threads (8 warps).
//   Y  [T][32][256]   QK [8][T][256] (pre-scaled)   Z [8][T][256]
// y staged once into XOR-swizzled smem (conflict-free in all phases).
// dots: warp c owns i4-chunk [8c,8c+8), lanes = m; y register-cached across
//       all 8 heads; cross-warp partial reduce through smem.
// softmax: warp-shuffle (warp h holds all 32 m in its lanes).
// z: 4 m-groups x 64 i4 columns, y register-reused across 8 heads, 4-way
//    partial reduce through smem, float4 coalesced store.
// Dynamic smem: 82944 B.
// ----------------------------------------------------------------------------
__global__ __launch_bounds__(256)
void attn_kernel(const float* __restrict__ Y,
                 const float* __restrict__ QK,
                 float* __restrict__ Z,
                 int T)
{
    extern __shared__ __align__(16) char smem_raw[];
    float4* ys4  = reinterpret_cast<float4*>(smem_raw);   // [32][64] swizzled
    float4* qks4 = ys4 + 2048;                            // [8][64]
    float*  pd   = reinterpret_cast<float*>(qks4 + 512);  // [8c][8h][32m]
    float*  attn = pd + 2048;                             // [8h][32m]
    float4* zp   = reinterpret_cast<float4*>(attn + 256); // [4g][8h][64i4]

    const int tid = threadIdx.x;
    const int t   = blockIdx.x;

    // ---- stage y (swizzled) and qk ----
    const float4* Y4 = reinterpret_cast<const float4*>(Y + (size_t)t * 32 * 256);
#pragma unroll 4
    for (int f = tid; f < 2048; f += 256) {
        int m = f >> 6, i4 = f & 63;
        ys4[m * 64 + ((i4 + m) & 63)] = Y4[f];
    }
    const float4* QK4 = reinterpret_cast<const float4*>(QK);
#pragma unroll
    for (int f = tid; f < 512; f += 256) {
        int h = f >> 6, i4 = f & 63;
        qks4[f] = QK4[((size_t)h * T + t) * 64 + i4];
    }
    __syncthreads();

    // ---- dots: warp c = i4-chunk, lane = m ----
    {
        const int c = tid >> 5, m = tid & 31;
        float4 yreg[8];
#pragma unroll
        for (int j = 0; j < 8; j++)
            yreg[j] = ys4[m * 64 + (((c << 3) + j + m) & 63)];
#pragma unroll
        for (int h = 0; h < 8; h++) {
            float s = 0.f;
#pragma unroll
            for (int j = 0; j < 8; j++) {
                float4 q4 = qks4[h * 64 + (c << 3) + j];
                s = fmaf(yreg[j].x, q4.x, s);
                s = fmaf(yreg[j].y, q4.y, s);
                s = fmaf(yreg[j].z, q4.z, s);
                s = fmaf(yreg[j].w, q4.w, s);
            }
            pd[(c * 8 + h) * 32 + m] = s;
        }
    }
    __syncthreads();

    // ---- reduce partials + softmax (warp = head) ----
    {
        const int h = tid >> 5, m = tid & 31;
        float d = 0.f;
#pragma unroll
        for (int cc = 0; cc < 8; cc++) d += pd[(cc * 8 + h) * 32 + m];
        float mx = d;
#pragma unroll
        for (int o = 16; o > 0; o >>= 1)
            mx = fmaxf(mx, __shfl_xor_sync(0xffffffffu, mx, o));
        float e = __expf(d - mx);
        float sm = e;
#pragma unroll
        for (int o = 16; o > 0; o >>= 1)
            sm += __shfl_xor_sync(0xffffffffu, sm, o);
        attn[h * 32 + m] = e / sm;
    }
    __syncthreads();

    // ---- z: group g = 8 m's, column i4; y register-reused across 8 heads ----
    {
        const int g = tid >> 6, i4 = tid & 63;
        float4 acc[8];
#pragma unroll
        for (int h = 0; h < 8; h++) acc[h] = make_float4(0.f, 0.f, 0.f, 0.f);
#pragma unroll
        for (int mm = 0; mm < 8; mm++) {
            int m = g * 8 + mm;
            float4 y4 = ys4[m * 64 + ((i4 + m) & 63)];
#pragma unroll
            for (int h = 0; h < 8; h++) {
                float a = attn[h * 32 + m];
                acc[h].x = fmaf(a, y4.x, acc[h].x);
                acc[h].y = fmaf(a, y4.y, acc[h].y);
                acc[h].z = fmaf(a, y4.z, acc[h].z);
                acc[h].w = fmaf(a, y4.w, acc[h].w);
            }
        }
#pragma unroll
        for (int h = 0; h < 8; h++)
            zp[(g * 8 + h) * 64 + i4] = acc[h];
    }
    __syncthreads();

    // ---- reduce 4 groups, store Z ----
    float4* Z4 = reinterpret_cast<float4*>(Z);
#pragma unroll
    for (int r = 0; r < 2; r++) {
        int idx = tid + (r << 8);
        int h = idx >> 6, i4 = idx & 63;
        float4 s0 = zp[(0  + h) * 64 + i4];
        float4 s1 = zp[(8  + h) * 64 + i4];
        float4 s2 = zp[(16 + h) * 64 + i4];
        float4 s3 = zp[(24 + h) * 64 + i4];
        float4 s;
        s.x = (s0.x + s1.x) + (s2.x + s3.x);
        s.y = (s0.y + s1.y) + (s2.y + s3.y);
        s.z = (s0.z + s1.z) + (s2.z + s3.z);
        s.w = (s0.w + s1.w) + (s2.w + s3.w);
        Z4[((size_t)h * T + t) * 64 + i4] = s;
    }
}

// ----------------------------------------------------------------------------
extern "C" void kernel_launch(void* const* d_in, const int* in_sizes, int n_in,
                              void* d_out, int out_size)
{
    const float* x    = (const float*)d_in[0];
    const float* y    = (const float*)d_in[1];
    const float* Wq   = (const float*)d_in[2];
    const float* Wkv  = (const float*)d_in[3];
    const float* Wout = (const float*)d_in[4];
    const float* bout = (const float*)d_in[5];
    float* out = (float*)d_out;

    const int T = in_sizes[0] / 256;   // b*n = 16384

    float *Q, *QK, *Z, *O1;
    cudaGetSymbolAddress((void**)&Q,  g_Q);
    cudaGetSymbolAddress((void**)&QK, g_QK);
    cudaGetSymbolAddress((void**)&Z,  g_Z);
    cudaGetSymbolAddress((void**)&O1, g_O1);

    const int ATTN_SMEM = 82944;
    cudaFuncSetAttribute(attn_kernel,
                         cudaFuncAttributeMaxDynamicSharedMemorySize, ATTN_SMEM);

    // K1: Q = X @ Wq   [T,256] = [T,256]@[256,256]
    gemm_kernel<128, 64, false><<<dim3(4, T / 128, 1), 256>>>(
        x, 256, 0,  Wq, 256, 0,  Q, 256, 0,  T, 256, 256, nullptr, 1.f);

    // K2: QK_h = Q_h @ Wk_h^T * SCALE   batched over h (z-dim)
    //     A = Q cols [h*32, h*32+32), B = Wkv rows as [N=256(i), K=32(d)]
    gemm_kernel<128, 64, true><<<dim3(4, T / 128, 8), 256>>>(
        Q, 256, 32,  Wkv, 512, 32,  QK, 256, (long)T * 256,
        T, 256, 32, nullptr, SCALE);

    // K3: fused dots/softmax/z
    attn_kernel<<<T, 256, ATTN_SMEM>>>(y, QK, Z, T);

    // K4: O_h = Z_h @ Wv_h   [T,32] per head, interleaved into O1[t][h*32+d]
    gemm_kernel<256, 32, false><<<dim3(1, T / 256, 8), 256>>>(
        Z, 256, (long)T * 256,  Wkv + 256, 512, 32,  O1, 256, 32,
        T, 32, 256, nullptr, 1.f);

    // K5: OUT = O1 @ Wout + bout
    gemm_kernel<128, 64, false><<<dim3(4, T / 128, 1), 256>>>(
        O1, 256, 0,  Wout, 256, 0,  out, 256, 0,
        T, 256, 256, bout, 1.f);
}